// round 7
// baseline (speedup 1.0000x reference)
#include <cuda_runtime.h>
#include <cstdint>

// Problem constants
#define BB     64
#define CC     20
#define NAA    5
#define HHH    19
#define WWW    19
#define HW     361      // 19*19
#define TT     50
#define NBB    1280     // B*C
#define A4     1805     // NA*H*W
#define CHN    30       // NA*(5+NCPA)
#define EPS12  1e-12f
#define RB     4                              // rows per band
#define BANDS  5
#define TILE   (NAA * RB * WWW)               // 380 cells per band-block
#define TPB    192
#define MAIN_BLOCKS (NBB * BANDS)             // 6400
#define CLS_N   (BB * A4)                     // 115520
#define CLS_BLOCKS ((CLS_N + TPB - 1) / TPB)  // 602
#define TOTB    (MAIN_BLOCKS + CLS_BLOCKS)
#define BIGS    1e18f

// Static scratch (no allocations; self-cleaning or overwritten every run)
__device__ int    g_bm[NBB][BANDS];           // gts per (nb, band)
__device__ float4 g_bgt[NBB][BANDS][TT];      // gl, gr, gtop, gbot
__device__ float  g_bgc[NBB][BANDS][TT];      // -0.375*gt_area
__device__ int    g_bn[NBB][BANDS];           // assignments per (nb, band)
__device__ int    g_bcell[NBB][BANDS][TT];
__device__ float  g_bval[NBB][BANDS][TT][5];  // tx, ty, tw, th, tconf
__device__ int    g_cnt[CLS_N];               // winners per (b, a4) across C
__device__ float  g_tsum[CLS_N];
__device__ double g_acc[3];                   // dense, cls nll, nsel
__device__ unsigned int g_done;

__device__ __forceinline__ float fsigm(float v) {
    return __fdividef(1.0f, 1.0f + __expf(-v));
}
__device__ __forceinline__ float softplus(float v) {
    return __logf(1.0f + __expf(v));
}

// ---------------------------------------------------------------------------
// One block (64 threads) per nb row. Computes gt boxes, winner assignments,
// and pre-compacts per-band gt lists + per-band assignment lists.
__global__ void k_assign(const float* __restrict__ out,
                         const float* __restrict__ target,
                         const float* __restrict__ anchors) {
    int nb = blockIdx.x;
    int t  = threadIdx.x;

    __shared__ float s_tg[TT * 5];
    __shared__ int   s_ng;
    __shared__ int   s_bm[BANDS], s_bn[BANDS];
    __shared__ int   s_cell[TT];

    if (t == 0) s_ng = TT;
    if (t < BANDS) { s_bm[t] = 0; s_bn[t] = 0; }
    const float* tg = target + (size_t)nb * TT * 5;
    for (int i = t; i < TT * 5; i += 64) s_tg[i] = tg[i];
    __syncthreads();

    if (t < TT && s_tg[t * 5 + 1] == 0.0f) atomicMin(&s_ng, t);
    __syncthreads();
    int ng = s_ng;

    float gx = 0.f, gy = 0.f, gw = 0.f, gh = 0.f, ct = 0.f;
    int gi = 0, gj = 0, bn = 0, cell = -1;
    float awb = 1.f, ahb = 1.f;

    if (t < ng) {
        ct = s_tg[t * 5 + 0];
        gx = s_tg[t * 5 + 1] * (float)WWW;
        gy = s_tg[t * 5 + 2] * (float)HHH;
        gw = s_tg[t * 5 + 3] * (float)WWW;
        gh = s_tg[t * 5 + 4] * (float)HHH;

        float best = -1.0f;
#pragma unroll
        for (int a = 0; a < NAA; a++) {
            float aw = __ldg(&anchors[2 * a]);
            float ah = __ldg(&anchors[2 * a + 1]);
            float inter = fminf(gw, aw) * fminf(gh, ah);
            float un = gw * gh + aw * ah - inter;
            float r = __fdividef(inter, fmaxf(un, EPS12));
            if (r > best) { best = r; bn = a; awb = aw; ahb = ah; }
        }
        gi = (int)gx;
        gj = (int)gy;
        cell = bn * HW + gj * WWW + gi;   // anchor-major cell id
        s_cell[t] = cell;

        // per-band gt list: gt matters only for rows hh in (gy-0.4gh-1, gy+0.4gh)
        float gl = gx - 0.5f * gw, gr = gx + 0.5f * gw;
        float gtop = gy - 0.5f * gh, gbot = gy + 0.5f * gh;
        float ylo = 0.9f * gtop + 0.1f * gbot;  // gy - 0.4*gh
        float yhi = 0.1f * gtop + 0.9f * gbot;  // gy + 0.4*gh
        float gcn = -0.375f * gw * gh;
#pragma unroll
        for (int bd = 0; bd < BANDS; bd++) {
            float h0 = (float)(bd * RB);
            if (h0 < yhi + 0.01f && h0 + (float)RB > ylo - 0.01f) {
                int pos = atomicAdd(&s_bm[bd], 1);
                g_bgt[nb][bd][pos] = make_float4(gl, gr, gtop, gbot);
                g_bgc[nb][bd][pos] = gcn;
            }
        }
    }
    __syncthreads();

    if (t < ng) {
        // last writer wins for this cell within this nb row
        bool win = true;
        for (int t2 = t + 1; t2 < ng; t2++)
            if (s_cell[t2] == cell) win = false;

        if (win) {
            int b = nb / CC;
            atomicAdd(&g_cnt[b * A4 + cell], 1);
            atomicAdd(&g_tsum[b * A4 + cell], ct);

            const float* ob = out + ((size_t)nb * CHN + bn * 6) * HW + gj * WWW + gi;
            float px = fsigm(ob[0])    + (float)gi;
            float py = fsigm(ob[HW])   + (float)gj;
            float pw = __expf(ob[2 * HW]) * awb;
            float ph = __expf(ob[3 * HW]) * ahb;

            float l  = fmaxf(gx - 0.5f * gw, px - 0.5f * pw);
            float r2 = fminf(gx + 0.5f * gw, px + 0.5f * pw);
            float tp = fmaxf(gy - 0.5f * gh, py - 0.5f * ph);
            float bt = fminf(gy + 0.5f * gh, py + 0.5f * ph);
            float inter = fmaxf(r2 - l, 0.0f) * fmaxf(bt - tp, 0.0f);
            float un = gw * gh + pw * ph - inter;
            float iou = __fdividef(inter, fmaxf(un, EPS12));

            int bd = gj / RB;
            int slot = atomicAdd(&s_bn[bd], 1);
            g_bcell[nb][bd][slot] = cell;
            g_bval[nb][bd][slot][0] = gx - (float)gi;
            g_bval[nb][bd][slot][1] = gy - (float)gj;
            g_bval[nb][bd][slot][2] = __logf(__fdividef(fmaxf(gw, EPS12), awb));
            g_bval[nb][bd][slot][3] = __logf(__fdividef(fmaxf(gh, EPS12), ahb));
            g_bval[nb][bd][slot][4] = iou;
        }
    }
    __syncthreads();
    if (t < BANDS) {
        g_bm[nb][t] = s_bm[t];
        g_bn[nb][t] = s_bn[t];
    }
}

// ---------------------------------------------------------------------------
// Fused dense losses (band-tiled, precompacted gts, 2 cells/thread) + class
// loss + final combine, ONE launch.
__global__ void __launch_bounds__(TPB, 7)
k_fused(const float* __restrict__ out,
        const float* __restrict__ anchors,
        float* __restrict__ res) {
    int tid = threadIdx.x;

    if (blockIdx.x < MAIN_BLOCKS) {
        int nb   = blockIdx.x / BANDS;
        int band = blockIdx.x - nb * BANDS;
        int h0   = band * RB;

        // ---- decode 2 cells & issue global loads early ----
        bool  lv[2];
        int   gidx[2], na_[2], ww_[2], hh_[2];
        float o_[2][5];
#pragma unroll
        for (int i = 0; i < 2; i++) {
            int c = tid + i * TPB;
            int na = c / (RB * WWW);
            int rem = c - na * (RB * WWW);
            int r = rem / WWW;
            int ww = rem - r * WWW;
            int hh = h0 + r;
            bool live = (c < TILE) && (hh < HHH);
            lv[i] = live; na_[i] = na; ww_[i] = ww; hh_[i] = hh;
            if (live) {
                int hw = hh * WWW + ww;
                gidx[i] = na * HW + hw;
                const float* ob = out + ((size_t)nb * CHN + na * 6) * HW + hw;
#pragma unroll
                for (int j = 0; j < 5; j++) o_[i][j] = ob[j * HW];
            } else {
                gidx[i] = -1;
#pragma unroll
                for (int j = 0; j < 5; j++) o_[i][j] = 0.0f;
            }
        }

        // ---- shared tables (precompacted per band) ----
        __shared__ float4 s_g[TT];
        __shared__ float  s_gcn[TT];
        __shared__ int    s_cell[TT];
        __shared__ float  s_val[TT][5];
        __shared__ uint32_t s_bits[57];

        int m    = g_bm[nb][band];
        int nasg = g_bn[nb][band];
        int mp   = ((m + 4) / 5) * 5;

        if (tid < 57) s_bits[tid] = 0u;
        for (int i = tid; i < mp; i += TPB) {
            if (i < m) {
                s_g[i]   = g_bgt[nb][band][i];
                s_gcn[i] = g_bgc[nb][band][i];
            } else {
                s_g[i]   = make_float4(0.f, 0.f, 0.f, 0.f);
                s_gcn[i] = -1e30f;
            }
        }
        for (int i = tid; i < nasg * 5; i += TPB)
            (&s_val[0][0])[i] = (&g_bval[nb][band][0][0])[i];
        __syncthreads();
        for (int i = tid; i < nasg; i += TPB) {
            int c = g_bcell[nb][band][i];
            s_cell[i] = c;
            atomicOr(&s_bits[c >> 5], 1u << (c & 31));
        }
        __syncthreads();

        // ---- per-cell pred box setup ----
        float pl[2], pr[2], pt[2], pb[2], k1[2], mm[2];
#pragma unroll
        for (int i = 0; i < 2; i++) {
            if (lv[i]) {
                float x = fsigm(o_[i][0]);
                float y = fsigm(o_[i][1]);
                float aw = __ldg(&anchors[2 * na_[i]]);
                float ah = __ldg(&anchors[2 * na_[i] + 1]);
                float px = x + (float)ww_[i];
                float py = y + (float)hh_[i];
                float pw = __expf(o_[i][2]) * aw;
                float ph = __expf(o_[i][3]) * ah;
                pl[i] = px - 0.5f * pw; pr[i] = px + 0.5f * pw;
                pt[i] = py - 0.5f * ph; pb[i] = py + 0.5f * ph;
                k1[i] = 0.375f * pw * ph;
            } else {
                pl[i] = BIGS; pr[i] = -BIGS;
                pt[i] = BIGS; pb[i] = -BIGS;
                k1[i] = 1e30f;
            }
            mm[i] = -1e30f;
        }

        // ---- filtered IoU>0.6 loop ----
#pragma unroll 5
        for (int t = 0; t < mp; t++) {
            float4 g = s_g[t];
            float gcn = s_gcn[t];
#pragma unroll
            for (int i = 0; i < 2; i++) {
                float iw = fminf(pr[i], g.y) - fmaxf(pl[i], g.x);
                float ih = fminf(pb[i], g.w) - fmaxf(pt[i], g.z);
                mm[i] = fmaxf(mm[i], fmaf(fmaxf(iw, 0.0f), ih, gcn));
            }
        }

        // ---- epilogue: softplus-BCE + MSE per cell ----
        // BCE(sigmoid(v), t) = softplus(v) - t*v   (clamp is a no-op here)
        double contrib = 0.0;
#pragma unroll
        for (int i = 0; i < 2; i++) {
            if (!lv[i]) continue;
            int idx = gidx[i];
            float o0 = o_[i][0], o1 = o_[i][1];
            float o2 = o_[i][2], o3 = o_[i][3];
            float conf = fsigm(o_[i][4]);

            float cfm = (mm[i] > k1[i]) ? 0.0f : 1.0f;
            float tx = 0.5f, ty = 0.5f, tw = 0.0f, th = 0.0f, tconf = 0.0f;
            if (s_bits[idx >> 5] & (1u << (idx & 31))) {
                for (int k = 0; k < nasg; k++) {
                    if (s_cell[k] == idx) {
                        cfm = 1.0f;
                        tx = s_val[k][0]; ty = s_val[k][1];
                        tw = s_val[k][2]; th = s_val[k][3];
                        tconf = s_val[k][4];
                    }
                }
            }
            float bxy = softplus(o0) - tx * o0 + softplus(o1) - ty * o1;
            float dw = o2 - tw, dh = o3 - th;
            float dc = cfm * (conf - tconf);
            contrib += (double)(bxy + 0.5f * (dw * dw + dh * dh) + 0.5f * dc * dc);
        }

#pragma unroll
        for (int o = 16; o > 0; o >>= 1)
            contrib += __shfl_down_sync(0xffffffffu, contrib, o);
        __shared__ double s_red[6];
        if ((tid & 31) == 0) s_red[tid >> 5] = contrib;
        __syncthreads();
        if (tid == 0) {
            double s = 0.0;
#pragma unroll
            for (int w = 0; w < 6; w++) s += s_red[w];
            atomicAdd(&g_acc[0], s);
        }
    } else {
        // ---- class-loss blocks (self-cleaning: reset g_cnt/g_tsum) ----
        int idx = (blockIdx.x - MAIN_BLOCKS) * TPB + tid;
        double nll = 0.0, ns = 0.0;
        if (idx < CLS_N) {
            int cnt = g_cnt[idx];
            if (cnt != 0) {
                float tsum = g_tsum[idx];
                g_cnt[idx] = 0;
                g_tsum[idx] = 0.0f;
                if (cnt == 1) {
                    int b  = idx / A4;
                    int a4 = idx - b * A4;
                    int na = a4 / HW;
                    int hw = a4 - na * HW;
                    int label = (int)tsum;
                    size_t obase = ((size_t)b * CC * CHN + na * 6 + 5) * HW + hw;
                    float mv = -1e30f, s = 0.0f, llab = 0.0f;
#pragma unroll
                    for (int c = 0; c < CC; c++) {
                        float l = out[obase + (size_t)c * CHN * HW];
                        if (c == label) llab = l;
                        if (l > mv) { s = s * __expf(mv - l) + 1.0f; mv = l; }
                        else        { s += __expf(l - mv); }
                    }
                    float lse = mv + __logf(s);
                    nll = (double)(lse - llab);
                    ns  = 1.0;
                }
            }
        }
#pragma unroll
        for (int o = 16; o > 0; o >>= 1) {
            nll += __shfl_down_sync(0xffffffffu, nll, o);
            ns  += __shfl_down_sync(0xffffffffu, ns,  o);
        }
        __shared__ double s_n[6], s_c[6];
        if ((tid & 31) == 0) { s_n[tid >> 5] = nll; s_c[tid >> 5] = ns; }
        __syncthreads();
        if (tid == 0) {
            double a = 0.0, bsum = 0.0;
#pragma unroll
            for (int w = 0; w < 6; w++) { a += s_n[w]; bsum += s_c[w]; }
            if (a != 0.0)    atomicAdd(&g_acc[1], a);
            if (bsum != 0.0) atomicAdd(&g_acc[2], bsum);
        }
    }

    // ---- last-block final combine (also resets g_acc for next replay) ----
    if (tid == 0) {
        __threadfence();
        unsigned int old = atomicAdd(&g_done, 1u);
        if (old == TOTB - 1) {
            double a0 = __longlong_as_double(
                atomicExch((unsigned long long*)&g_acc[0], 0ULL));
            double a1 = __longlong_as_double(
                atomicExch((unsigned long long*)&g_acc[1], 0ULL));
            double a2 = __longlong_as_double(
                atomicExch((unsigned long long*)&g_acc[2], 0ULL));
            double N = (double)NBB * (double)A4;
            res[0] = (float)(a0 / N + a1 / fmax(a2, 1.0));
            g_done = 0;
        }
    }
}

// ---------------------------------------------------------------------------
extern "C" void kernel_launch(void* const* d_in, const int* in_sizes, int n_in,
                              void* d_out, int out_size) {
    const float* out_t   = (const float*)d_in[0];
    const float* target  = (const float*)d_in[1];
    const float* anchors = (const float*)d_in[2];
    float* res = (float*)d_out;

    k_assign<<<NBB, 64>>>(out_t, target, anchors);
    k_fused<<<TOTB, TPB>>>(out_t, anchors, res);
}

// round 8
// speedup vs baseline: 1.1274x; 1.1274x over previous
#include <cuda_runtime.h>
#include <cstdint>

// Problem constants
#define BB     64
#define CC     20
#define NAA    5
#define HHH    19
#define WWW    19
#define HW     361      // 19*19
#define TT     50
#define NBB    1280     // B*C
#define A4     1805     // NA*H*W
#define CHN    30       // NA*(5+NCPA)
#define EPS12  1e-12f
#define RB     4                              // rows per band
#define BANDS  5
#define TILE   (NAA * RB * WWW)               // 380 cells per band-block
#define MAIN_BLOCKS (NBB * BANDS)             // 6400
#define CLS_N   (BB * A4)                     // 115520
#define CLS_BLOCKS ((CLS_N + 127) / 128)      // 903
#define TOTB    (MAIN_BLOCKS + CLS_BLOCKS)
#define BIGS    1e18f

// Static scratch (no allocations; self-cleaning or overwritten every run)
__device__ int    g_bm[NBB][BANDS];           // gts per (nb, band)
__device__ float4 g_bgt[NBB][BANDS][TT];      // gl, gr, gtop, gbot
__device__ float  g_bgc[NBB][BANDS][TT];      // -0.375*gt_area
__device__ int    g_bn[NBB][BANDS];           // assignments per (nb, band)
__device__ int    g_bcell[NBB][BANDS][TT];
__device__ float  g_bval[NBB][BANDS][TT][5];  // tx, ty, tw, th, tconf
__device__ int    g_cnt[CLS_N];               // winners per (b, a4) across C
__device__ float  g_tsum[CLS_N];
__device__ float  g_accf[3];                  // dense, cls nll, nsel (float)
__device__ unsigned int g_done;

__device__ __forceinline__ float fsigm(float v) {
    return __fdividef(1.0f, 1.0f + __expf(-v));
}
__device__ __forceinline__ float softplus(float v) {
    return __logf(1.0f + __expf(v));
}

// ---------------------------------------------------------------------------
// One block (64 threads) per nb row. Computes gt boxes, winner assignments,
// and pre-compacts per-band gt lists + per-band assignment lists.
__global__ void k_assign(const float* __restrict__ out,
                         const float* __restrict__ target,
                         const float* __restrict__ anchors) {
    int nb = blockIdx.x;
    int t  = threadIdx.x;

    __shared__ float s_tg[TT * 5];
    __shared__ int   s_ng;
    __shared__ int   s_bm[BANDS], s_bn[BANDS];
    __shared__ int   s_cell[TT];

    if (t == 0) s_ng = TT;
    if (t < BANDS) { s_bm[t] = 0; s_bn[t] = 0; }
    const float* tg = target + (size_t)nb * TT * 5;
    for (int i = t; i < TT * 5; i += 64) s_tg[i] = tg[i];
    __syncthreads();

    if (t < TT && s_tg[t * 5 + 1] == 0.0f) atomicMin(&s_ng, t);
    __syncthreads();
    int ng = s_ng;

    float gx = 0.f, gy = 0.f, gw = 0.f, gh = 0.f, ct = 0.f;
    int gi = 0, gj = 0, bn = 0, cell = -1;
    float awb = 1.f, ahb = 1.f;

    if (t < ng) {
        ct = s_tg[t * 5 + 0];
        gx = s_tg[t * 5 + 1] * (float)WWW;
        gy = s_tg[t * 5 + 2] * (float)HHH;
        gw = s_tg[t * 5 + 3] * (float)WWW;
        gh = s_tg[t * 5 + 4] * (float)HHH;

        float best = -1.0f;
#pragma unroll
        for (int a = 0; a < NAA; a++) {
            float aw = __ldg(&anchors[2 * a]);
            float ah = __ldg(&anchors[2 * a + 1]);
            float inter = fminf(gw, aw) * fminf(gh, ah);
            float un = gw * gh + aw * ah - inter;
            float r = __fdividef(inter, fmaxf(un, EPS12));
            if (r > best) { best = r; bn = a; awb = aw; ahb = ah; }
        }
        gi = (int)gx;
        gj = (int)gy;
        cell = bn * HW + gj * WWW + gi;   // anchor-major cell id
        s_cell[t] = cell;

        // per-band gt list: gt matters only for rows hh in (gy-0.4gh-1, gy+0.4gh)
        float gl = gx - 0.5f * gw, gr = gx + 0.5f * gw;
        float gtop = gy - 0.5f * gh, gbot = gy + 0.5f * gh;
        float ylo = 0.9f * gtop + 0.1f * gbot;  // gy - 0.4*gh
        float yhi = 0.1f * gtop + 0.9f * gbot;  // gy + 0.4*gh
        float gcn = -0.375f * gw * gh;
#pragma unroll
        for (int bd = 0; bd < BANDS; bd++) {
            float h0 = (float)(bd * RB);
            if (h0 < yhi + 0.01f && h0 + (float)RB > ylo - 0.01f) {
                int pos = atomicAdd(&s_bm[bd], 1);
                g_bgt[nb][bd][pos] = make_float4(gl, gr, gtop, gbot);
                g_bgc[nb][bd][pos] = gcn;
            }
        }
    }
    __syncthreads();

    if (t < ng) {
        // last writer wins for this cell within this nb row
        bool win = true;
        for (int t2 = t + 1; t2 < ng; t2++)
            if (s_cell[t2] == cell) win = false;

        if (win) {
            int b = nb / CC;
            atomicAdd(&g_cnt[b * A4 + cell], 1);
            atomicAdd(&g_tsum[b * A4 + cell], ct);

            const float* ob = out + ((size_t)nb * CHN + bn * 6) * HW + gj * WWW + gi;
            float px = fsigm(ob[0])    + (float)gi;
            float py = fsigm(ob[HW])   + (float)gj;
            float pw = __expf(ob[2 * HW]) * awb;
            float ph = __expf(ob[3 * HW]) * ahb;

            float l  = fmaxf(gx - 0.5f * gw, px - 0.5f * pw);
            float r2 = fminf(gx + 0.5f * gw, px + 0.5f * pw);
            float tp = fmaxf(gy - 0.5f * gh, py - 0.5f * ph);
            float bt = fminf(gy + 0.5f * gh, py + 0.5f * ph);
            float inter = fmaxf(r2 - l, 0.0f) * fmaxf(bt - tp, 0.0f);
            float un = gw * gh + pw * ph - inter;
            float iou = __fdividef(inter, fmaxf(un, EPS12));

            int bd = gj / RB;
            int slot = atomicAdd(&s_bn[bd], 1);
            g_bcell[nb][bd][slot] = cell;
            g_bval[nb][bd][slot][0] = gx - (float)gi;
            g_bval[nb][bd][slot][1] = gy - (float)gj;
            g_bval[nb][bd][slot][2] = __logf(__fdividef(fmaxf(gw, EPS12), awb));
            g_bval[nb][bd][slot][3] = __logf(__fdividef(fmaxf(gh, EPS12), ahb));
            g_bval[nb][bd][slot][4] = iou;
        }
    }
    __syncthreads();
    if (t < BANDS) {
        g_bm[nb][t] = s_bm[t];
        g_bn[nb][t] = s_bn[t];
    }
}

// ---------------------------------------------------------------------------
// Fused dense losses (band-tiled, precompacted gts, 3 cells/thread, float
// accumulation) + class loss + final combine, ONE launch.
__global__ void __launch_bounds__(128, 10)
k_fused(const float* __restrict__ out,
        const float* __restrict__ anchors,
        float* __restrict__ res) {
    int tid = threadIdx.x;

    if (blockIdx.x < MAIN_BLOCKS) {
        int nb   = blockIdx.x / BANDS;
        int band = blockIdx.x - nb * BANDS;
        int h0   = band * RB;

        // ---- decode 3 cells & issue global loads early ----
        bool  lv[3];
        int   gidx[3], na_[3], ww_[3], hh_[3];
        float o_[3][5];
#pragma unroll
        for (int i = 0; i < 3; i++) {
            int c = tid + i * 128;
            int na = c / (RB * WWW);
            int rem = c - na * (RB * WWW);
            int r = rem / WWW;
            int ww = rem - r * WWW;
            int hh = h0 + r;
            bool live = (c < TILE) && (hh < HHH);
            lv[i] = live; na_[i] = na; ww_[i] = ww; hh_[i] = hh;
            if (live) {
                int hw = hh * WWW + ww;
                gidx[i] = na * HW + hw;
                const float* ob = out + ((size_t)nb * CHN + na * 6) * HW + hw;
#pragma unroll
                for (int j = 0; j < 5; j++) o_[i][j] = ob[j * HW];
            } else {
                gidx[i] = -1;
#pragma unroll
                for (int j = 0; j < 5; j++) o_[i][j] = 0.0f;
            }
        }

        // ---- shared tables (precompacted per band) ----
        __shared__ float4 s_g[TT];
        __shared__ float  s_gcn[TT];
        __shared__ int    s_cell[TT];
        __shared__ float  s_val[TT][5];
        __shared__ uint32_t s_bits[57];

        int m    = g_bm[nb][band];
        int nasg = g_bn[nb][band];
        int mp   = ((m + 4) / 5) * 5;

        if (tid < 57) s_bits[tid] = 0u;
        for (int i = tid; i < mp; i += 128) {
            if (i < m) {
                s_g[i]   = g_bgt[nb][band][i];
                s_gcn[i] = g_bgc[nb][band][i];
            } else {
                s_g[i]   = make_float4(0.f, 0.f, 0.f, 0.f);
                s_gcn[i] = -1e30f;
            }
        }
        for (int i = tid; i < nasg * 5; i += 128)
            (&s_val[0][0])[i] = (&g_bval[nb][band][0][0])[i];
        __syncthreads();
        for (int i = tid; i < nasg; i += 128) {
            int c = g_bcell[nb][band][i];
            s_cell[i] = c;
            atomicOr(&s_bits[c >> 5], 1u << (c & 31));
        }
        __syncthreads();

        // ---- per-cell pred box setup ----
        float pl[3], pr[3], pt[3], pb[3], k1[3], mm[3];
#pragma unroll
        for (int i = 0; i < 3; i++) {
            if (lv[i]) {
                float x = fsigm(o_[i][0]);
                float y = fsigm(o_[i][1]);
                float aw = __ldg(&anchors[2 * na_[i]]);
                float ah = __ldg(&anchors[2 * na_[i] + 1]);
                float px = x + (float)ww_[i];
                float py = y + (float)hh_[i];
                float pw = __expf(o_[i][2]) * aw;
                float ph = __expf(o_[i][3]) * ah;
                pl[i] = px - 0.5f * pw; pr[i] = px + 0.5f * pw;
                pt[i] = py - 0.5f * ph; pb[i] = py + 0.5f * ph;
                k1[i] = 0.375f * pw * ph;
            } else {
                pl[i] = BIGS; pr[i] = -BIGS;
                pt[i] = BIGS; pb[i] = -BIGS;
                k1[i] = 1e30f;
            }
            mm[i] = -1e30f;
        }

        // ---- filtered IoU>0.6 loop (9 ops/cell/iter, 3-way ILP) ----
#pragma unroll 5
        for (int t = 0; t < mp; t++) {
            float4 g = s_g[t];
            float gcn = s_gcn[t];
#pragma unroll
            for (int i = 0; i < 3; i++) {
                float iw = fminf(pr[i], g.y) - fmaxf(pl[i], g.x);
                float ih = fminf(pb[i], g.w) - fmaxf(pt[i], g.z);
                mm[i] = fmaxf(mm[i], fmaf(fmaxf(iw, 0.0f), ih, gcn));
            }
        }

        // ---- epilogue: softplus-BCE + MSE per cell (float accum) ----
        float contrib = 0.0f;
#pragma unroll
        for (int i = 0; i < 3; i++) {
            if (!lv[i]) continue;
            int idx = gidx[i];
            float o0 = o_[i][0], o1 = o_[i][1];
            float o2 = o_[i][2], o3 = o_[i][3];
            float conf = fsigm(o_[i][4]);

            float cfm = (mm[i] > k1[i]) ? 0.0f : 1.0f;
            float tx = 0.5f, ty = 0.5f, tw = 0.0f, th = 0.0f, tconf = 0.0f;
            if (s_bits[idx >> 5] & (1u << (idx & 31))) {
                for (int k = 0; k < nasg; k++) {
                    if (s_cell[k] == idx) {
                        cfm = 1.0f;
                        tx = s_val[k][0]; ty = s_val[k][1];
                        tw = s_val[k][2]; th = s_val[k][3];
                        tconf = s_val[k][4];
                    }
                }
            }
            // BCE(sigmoid(v), t) = softplus(v) - t*v  (clamp is a no-op here)
            float bxy = softplus(o0) - tx * o0 + softplus(o1) - ty * o1;
            float dw = o2 - tw, dh = o3 - th;
            float dc = cfm * (conf - tconf);
            contrib += bxy + 0.5f * (dw * dw + dh * dh) + 0.5f * dc * dc;
        }

#pragma unroll
        for (int o = 16; o > 0; o >>= 1)
            contrib += __shfl_down_sync(0xffffffffu, contrib, o);
        __shared__ float s_red[4];
        if ((tid & 31) == 0) s_red[tid >> 5] = contrib;
        __syncthreads();
        if (tid == 0)
            atomicAdd(&g_accf[0], s_red[0] + s_red[1] + s_red[2] + s_red[3]);
    } else {
        // ---- class-loss blocks (self-cleaning: reset g_cnt/g_tsum) ----
        int idx = (blockIdx.x - MAIN_BLOCKS) * 128 + tid;
        float nll = 0.0f, ns = 0.0f;
        if (idx < CLS_N) {
            int cnt = g_cnt[idx];
            if (cnt != 0) {
                float tsum = g_tsum[idx];
                g_cnt[idx] = 0;
                g_tsum[idx] = 0.0f;
                if (cnt == 1) {
                    int b  = idx / A4;
                    int a4 = idx - b * A4;
                    int na = a4 / HW;
                    int hw = a4 - na * HW;
                    int label = (int)tsum;
                    size_t obase = ((size_t)b * CC * CHN + na * 6 + 5) * HW + hw;
                    float mv = -1e30f, s = 0.0f, llab = 0.0f;
#pragma unroll
                    for (int c = 0; c < CC; c++) {
                        float l = out[obase + (size_t)c * CHN * HW];
                        if (c == label) llab = l;
                        if (l > mv) { s = s * __expf(mv - l) + 1.0f; mv = l; }
                        else        { s += __expf(l - mv); }
                    }
                    float lse = mv + __logf(s);
                    nll = lse - llab;
                    ns  = 1.0f;
                }
            }
        }
#pragma unroll
        for (int o = 16; o > 0; o >>= 1) {
            nll += __shfl_down_sync(0xffffffffu, nll, o);
            ns  += __shfl_down_sync(0xffffffffu, ns,  o);
        }
        __shared__ float s_n[4], s_c[4];
        if ((tid & 31) == 0) { s_n[tid >> 5] = nll; s_c[tid >> 5] = ns; }
        __syncthreads();
        if (tid == 0) {
            float a = s_n[0] + s_n[1] + s_n[2] + s_n[3];
            float bsum = s_c[0] + s_c[1] + s_c[2] + s_c[3];
            if (a != 0.0f)    atomicAdd(&g_accf[1], a);
            if (bsum != 0.0f) atomicAdd(&g_accf[2], bsum);
        }
    }

    // ---- last-block final combine (also resets g_accf for next replay) ----
    if (tid == 0) {
        __threadfence();
        unsigned int old = atomicAdd(&g_done, 1u);
        if (old == TOTB - 1) {
            float a0 = atomicExch(&g_accf[0], 0.0f);
            float a1 = atomicExch(&g_accf[1], 0.0f);
            float a2 = atomicExch(&g_accf[2], 0.0f);
            double N = (double)NBB * (double)A4;
            res[0] = (float)((double)a0 / N +
                             (double)a1 / fmax((double)a2, 1.0));
            g_done = 0;
        }
    }
}

// ---------------------------------------------------------------------------
extern "C" void kernel_launch(void* const* d_in, const int* in_sizes, int n_in,
                              void* d_out, int out_size) {
    const float* out_t   = (const float*)d_in[0];
    const float* target  = (const float*)d_in[1];
    const float* anchors = (const float*)d_in[2];
    float* res = (float*)d_out;

    k_assign<<<NBB, 64>>>(out_t, target, anchors);
    k_fused<<<TOTB, 128>>>(out_t, anchors, res);
}

// round 9
// speedup vs baseline: 1.6857x; 1.4952x over previous
#include <cuda_runtime.h>
#include <cstdint>

// Problem constants
#define BB     64
#define CC     20
#define NAA    5
#define HHH    19
#define WWW    19
#define HW     361      // 19*19
#define TT     50
#define NBB    1280     // B*C
#define A4     1805     // NA*H*W
#define CHN    30       // NA*(5+NCPA)
#define EPS12  1e-12f
#define RB     4                              // rows per band
#define BANDS  5
#define TILE   (NAA * RB * WWW)               // 380 cells per band-block
#define MAIN_BLOCKS (NBB * BANDS)             // 6400
#define CLS_N   (BB * A4)                     // 115520
#define CLS_BLOCKS ((CLS_N + 127) / 128)      // 903
#define TOTB    (MAIN_BLOCKS + CLS_BLOCKS)
#define BIGS    1e18f

// Static scratch (no allocations; self-cleaning or overwritten every run)
__device__ int    g_bm[NBB][BANDS];           // gts per (nb, band)
__device__ float4 g_bgt[NBB][BANDS][TT];      // gl, gr, gtop, gbot
__device__ float  g_bgc[NBB][BANDS][TT];      // -0.375*gt_area
__device__ int    g_bn[NBB][BANDS];           // assignments per (nb, band)
__device__ int    g_bcell[NBB][BANDS][TT];
__device__ float  g_bval[NBB][BANDS][TT][5];  // tx, ty, tw, th, tconf
__device__ int    g_cnt[CLS_N];               // winners per (b, a4) across C
__device__ float  g_tsum[CLS_N];
__device__ float  g_accf[3];                  // dense, cls nll, nsel (float)
__device__ unsigned int g_done;

__device__ __forceinline__ float fsigm(float v) {
    return __fdividef(1.0f, 1.0f + __expf(-v));
}
__device__ __forceinline__ float softplus(float v) {
    return __logf(1.0f + __expf(v));
}

// ---------------------------------------------------------------------------
// One block (64 threads) per nb row. Computes gt boxes, winner assignments,
// and pre-compacts per-band gt lists + per-band assignment lists.
__global__ void k_assign(const float* __restrict__ out,
                         const float* __restrict__ target,
                         const float* __restrict__ anchors) {
    int nb = blockIdx.x;
    int t  = threadIdx.x;

    __shared__ float s_tg[TT * 5];
    __shared__ int   s_ng;
    __shared__ int   s_bm[BANDS], s_bn[BANDS];
    __shared__ int   s_cell[TT];

    if (t == 0) s_ng = TT;
    if (t < BANDS) { s_bm[t] = 0; s_bn[t] = 0; }
    const float* tg = target + (size_t)nb * TT * 5;
    for (int i = t; i < TT * 5; i += 64) s_tg[i] = tg[i];
    __syncthreads();

    if (t < TT && s_tg[t * 5 + 1] == 0.0f) atomicMin(&s_ng, t);
    __syncthreads();
    int ng = s_ng;

    float gx = 0.f, gy = 0.f, gw = 0.f, gh = 0.f, ct = 0.f;
    int gi = 0, gj = 0, bn = 0, cell = -1;
    float awb = 1.f, ahb = 1.f;

    if (t < ng) {
        ct = s_tg[t * 5 + 0];
        gx = s_tg[t * 5 + 1] * (float)WWW;
        gy = s_tg[t * 5 + 2] * (float)HHH;
        gw = s_tg[t * 5 + 3] * (float)WWW;
        gh = s_tg[t * 5 + 4] * (float)HHH;

        float best = -1.0f;
#pragma unroll
        for (int a = 0; a < NAA; a++) {
            float aw = __ldg(&anchors[2 * a]);
            float ah = __ldg(&anchors[2 * a + 1]);
            float inter = fminf(gw, aw) * fminf(gh, ah);
            float un = gw * gh + aw * ah - inter;
            float r = __fdividef(inter, fmaxf(un, EPS12));
            if (r > best) { best = r; bn = a; awb = aw; ahb = ah; }
        }
        gi = (int)gx;
        gj = (int)gy;
        cell = bn * HW + gj * WWW + gi;   // anchor-major cell id
        s_cell[t] = cell;

        // per-band gt list: gt matters only for rows hh in (gy-0.4gh-1, gy+0.4gh)
        float gl = gx - 0.5f * gw, gr = gx + 0.5f * gw;
        float gtop = gy - 0.5f * gh, gbot = gy + 0.5f * gh;
        float ylo = 0.9f * gtop + 0.1f * gbot;  // gy - 0.4*gh
        float yhi = 0.1f * gtop + 0.9f * gbot;  // gy + 0.4*gh
        float gcn = -0.375f * gw * gh;
#pragma unroll
        for (int bd = 0; bd < BANDS; bd++) {
            float h0 = (float)(bd * RB);
            if (h0 < yhi + 0.01f && h0 + (float)RB > ylo - 0.01f) {
                int pos = atomicAdd(&s_bm[bd], 1);
                g_bgt[nb][bd][pos] = make_float4(gl, gr, gtop, gbot);
                g_bgc[nb][bd][pos] = gcn;
            }
        }
    }
    __syncthreads();

    if (t < ng) {
        // last writer wins for this cell within this nb row
        bool win = true;
        for (int t2 = t + 1; t2 < ng; t2++)
            if (s_cell[t2] == cell) win = false;

        if (win) {
            int b = nb / CC;
            atomicAdd(&g_cnt[b * A4 + cell], 1);
            atomicAdd(&g_tsum[b * A4 + cell], ct);

            const float* ob = out + ((size_t)nb * CHN + bn * 6) * HW + gj * WWW + gi;
            float px = fsigm(ob[0])    + (float)gi;
            float py = fsigm(ob[HW])   + (float)gj;
            float pw = __expf(ob[2 * HW]) * awb;
            float ph = __expf(ob[3 * HW]) * ahb;

            float l  = fmaxf(gx - 0.5f * gw, px - 0.5f * pw);
            float r2 = fminf(gx + 0.5f * gw, px + 0.5f * pw);
            float tp = fmaxf(gy - 0.5f * gh, py - 0.5f * ph);
            float bt = fminf(gy + 0.5f * gh, py + 0.5f * ph);
            float inter = fmaxf(r2 - l, 0.0f) * fmaxf(bt - tp, 0.0f);
            float un = gw * gh + pw * ph - inter;
            float iou = __fdividef(inter, fmaxf(un, EPS12));

            int bd = gj / RB;
            int slot = atomicAdd(&s_bn[bd], 1);
            g_bcell[nb][bd][slot] = cell;
            g_bval[nb][bd][slot][0] = gx - (float)gi;
            g_bval[nb][bd][slot][1] = gy - (float)gj;
            g_bval[nb][bd][slot][2] = __logf(__fdividef(fmaxf(gw, EPS12), awb));
            g_bval[nb][bd][slot][3] = __logf(__fdividef(fmaxf(gh, EPS12), ahb));
            g_bval[nb][bd][slot][4] = iou;
        }
    }
    __syncthreads();
    if (t < BANDS) {
        g_bm[nb][t] = s_bm[t];
        g_bn[nb][t] = s_bn[t];
    }
}

// ---------------------------------------------------------------------------
// Fused dense losses (band-tiled, precompacted gts, 3 cells/thread, float
// accumulation) + class loss + final combine, ONE launch.
// launch_bounds(128, 8): allow up to 64 regs — NO spills (R8's (128,10)
// forced 48 regs and spilled, costing more instructions than occupancy won).
__global__ void __launch_bounds__(128, 8)
k_fused(const float* __restrict__ out,
        const float* __restrict__ anchors,
        float* __restrict__ res) {
    int tid = threadIdx.x;

    if (blockIdx.x < MAIN_BLOCKS) {
        int nb   = blockIdx.x / BANDS;
        int band = blockIdx.x - nb * BANDS;
        int h0   = band * RB;

        // ---- decode 3 cells & issue global loads early ----
        bool  lv[3];
        int   gidx[3], na_[3], ww_[3], hh_[3];
        float o_[3][5];
#pragma unroll
        for (int i = 0; i < 3; i++) {
            int c = tid + i * 128;
            int na = c / (RB * WWW);
            int rem = c - na * (RB * WWW);
            int r = rem / WWW;
            int ww = rem - r * WWW;
            int hh = h0 + r;
            bool live = (c < TILE) && (hh < HHH);
            lv[i] = live; na_[i] = na; ww_[i] = ww; hh_[i] = hh;
            if (live) {
                int hw = hh * WWW + ww;
                gidx[i] = na * HW + hw;
                const float* ob = out + ((size_t)nb * CHN + na * 6) * HW + hw;
#pragma unroll
                for (int j = 0; j < 5; j++) o_[i][j] = ob[j * HW];
            } else {
                gidx[i] = -1;
#pragma unroll
                for (int j = 0; j < 5; j++) o_[i][j] = 0.0f;
            }
        }

        // ---- shared tables (precompacted per band) ----
        __shared__ float4 s_g[TT];
        __shared__ float  s_gcn[TT];
        __shared__ int    s_cell[TT];
        __shared__ float  s_val[TT][5];
        __shared__ uint32_t s_bits[57];

        int m    = g_bm[nb][band];
        int nasg = g_bn[nb][band];
        int mp   = ((m + 4) / 5) * 5;

        if (tid < 57) s_bits[tid] = 0u;
        for (int i = tid; i < mp; i += 128) {
            if (i < m) {
                s_g[i]   = g_bgt[nb][band][i];
                s_gcn[i] = g_bgc[nb][band][i];
            } else {
                s_g[i]   = make_float4(0.f, 0.f, 0.f, 0.f);
                s_gcn[i] = -1e30f;
            }
        }
        for (int i = tid; i < nasg * 5; i += 128)
            (&s_val[0][0])[i] = (&g_bval[nb][band][0][0])[i];
        __syncthreads();
        for (int i = tid; i < nasg; i += 128) {
            int c = g_bcell[nb][band][i];
            s_cell[i] = c;
            atomicOr(&s_bits[c >> 5], 1u << (c & 31));
        }
        __syncthreads();

        // ---- per-cell pred box setup ----
        float pl[3], pr[3], pt[3], pb[3], k1[3], mm[3];
#pragma unroll
        for (int i = 0; i < 3; i++) {
            if (lv[i]) {
                float x = fsigm(o_[i][0]);
                float y = fsigm(o_[i][1]);
                float aw = __ldg(&anchors[2 * na_[i]]);
                float ah = __ldg(&anchors[2 * na_[i] + 1]);
                float px = x + (float)ww_[i];
                float py = y + (float)hh_[i];
                float pw = __expf(o_[i][2]) * aw;
                float ph = __expf(o_[i][3]) * ah;
                pl[i] = px - 0.5f * pw; pr[i] = px + 0.5f * pw;
                pt[i] = py - 0.5f * ph; pb[i] = py + 0.5f * ph;
                k1[i] = 0.375f * pw * ph;
            } else {
                pl[i] = BIGS; pr[i] = -BIGS;
                pt[i] = BIGS; pb[i] = -BIGS;
                k1[i] = 1e30f;
            }
            mm[i] = -1e30f;
        }

        // ---- filtered IoU>0.6 loop (9 ops/cell/iter, 3-way ILP) ----
#pragma unroll 5
        for (int t = 0; t < mp; t++) {
            float4 g = s_g[t];
            float gcn = s_gcn[t];
#pragma unroll
            for (int i = 0; i < 3; i++) {
                float iw = fminf(pr[i], g.y) - fmaxf(pl[i], g.x);
                float ih = fminf(pb[i], g.w) - fmaxf(pt[i], g.z);
                mm[i] = fmaxf(mm[i], fmaf(fmaxf(iw, 0.0f), ih, gcn));
            }
        }

        // ---- epilogue: softplus-BCE + MSE per cell (float accum) ----
        float contrib = 0.0f;
#pragma unroll
        for (int i = 0; i < 3; i++) {
            if (!lv[i]) continue;
            int idx = gidx[i];
            float o0 = o_[i][0], o1 = o_[i][1];
            float o2 = o_[i][2], o3 = o_[i][3];
            float conf = fsigm(o_[i][4]);

            float cfm = (mm[i] > k1[i]) ? 0.0f : 1.0f;
            float tx = 0.5f, ty = 0.5f, tw = 0.0f, th = 0.0f, tconf = 0.0f;
            if (s_bits[idx >> 5] & (1u << (idx & 31))) {
                for (int k = 0; k < nasg; k++) {
                    if (s_cell[k] == idx) {
                        cfm = 1.0f;
                        tx = s_val[k][0]; ty = s_val[k][1];
                        tw = s_val[k][2]; th = s_val[k][3];
                        tconf = s_val[k][4];
                    }
                }
            }
            // BCE(sigmoid(v), t) = softplus(v) - t*v  (clamp is a no-op here)
            float bxy = softplus(o0) - tx * o0 + softplus(o1) - ty * o1;
            float dw = o2 - tw, dh = o3 - th;
            float dc = cfm * (conf - tconf);
            contrib += bxy + 0.5f * (dw * dw + dh * dh) + 0.5f * dc * dc;
        }

#pragma unroll
        for (int o = 16; o > 0; o >>= 1)
            contrib += __shfl_down_sync(0xffffffffu, contrib, o);
        __shared__ float s_red[4];
        if ((tid & 31) == 0) s_red[tid >> 5] = contrib;
        __syncthreads();
        if (tid == 0)
            atomicAdd(&g_accf[0], s_red[0] + s_red[1] + s_red[2] + s_red[3]);
    } else {
        // ---- class-loss blocks (self-cleaning: reset g_cnt/g_tsum) ----
        int idx = (blockIdx.x - MAIN_BLOCKS) * 128 + tid;
        float nll = 0.0f, ns = 0.0f;
        if (idx < CLS_N) {
            int cnt = g_cnt[idx];
            if (cnt != 0) {
                float tsum = g_tsum[idx];
                g_cnt[idx] = 0;
                g_tsum[idx] = 0.0f;
                if (cnt == 1) {
                    int b  = idx / A4;
                    int a4 = idx - b * A4;
                    int na = a4 / HW;
                    int hw = a4 - na * HW;
                    int label = (int)tsum;
                    size_t obase = ((size_t)b * CC * CHN + na * 6 + 5) * HW + hw;
                    float mv = -1e30f, s = 0.0f, llab = 0.0f;
#pragma unroll
                    for (int c = 0; c < CC; c++) {
                        float l = out[obase + (size_t)c * CHN * HW];
                        if (c == label) llab = l;
                        if (l > mv) { s = s * __expf(mv - l) + 1.0f; mv = l; }
                        else        { s += __expf(l - mv); }
                    }
                    float lse = mv + __logf(s);
                    nll = lse - llab;
                    ns  = 1.0f;
                }
            }
        }
#pragma unroll
        for (int o = 16; o > 0; o >>= 1) {
            nll += __shfl_down_sync(0xffffffffu, nll, o);
            ns  += __shfl_down_sync(0xffffffffu, ns,  o);
        }
        __shared__ float s_n[4], s_c[4];
        if ((tid & 31) == 0) { s_n[tid >> 5] = nll; s_c[tid >> 5] = ns; }
        __syncthreads();
        if (tid == 0) {
            float a = s_n[0] + s_n[1] + s_n[2] + s_n[3];
            float bsum = s_c[0] + s_c[1] + s_c[2] + s_c[3];
            if (a != 0.0f)    atomicAdd(&g_accf[1], a);
            if (bsum != 0.0f) atomicAdd(&g_accf[2], bsum);
        }
    }

    // ---- last-block final combine (also resets g_accf for next replay) ----
    if (tid == 0) {
        __threadfence();
        unsigned int old = atomicAdd(&g_done, 1u);
        if (old == TOTB - 1) {
            float a0 = atomicExch(&g_accf[0], 0.0f);
            float a1 = atomicExch(&g_accf[1], 0.0f);
            float a2 = atomicExch(&g_accf[2], 0.0f);
            double N = (double)NBB * (double)A4;
            res[0] = (float)((double)a0 / N +
                             (double)a1 / fmax((double)a2, 1.0));
            g_done = 0;
        }
    }
}

// ---------------------------------------------------------------------------
extern "C" void kernel_launch(void* const* d_in, const int* in_sizes, int n_in,
                              void* d_out, int out_size) {
    const float* out_t   = (const float*)d_in[0];
    const float* target  = (const float*)d_in[1];
    const float* anchors = (const float*)d_in[2];
    float* res = (float*)d_out;

    k_assign<<<NBB, 64>>>(out_t, target, anchors);
    k_fused<<<TOTB, 128>>>(out_t, anchors, res);
}

// round 10
// speedup vs baseline: 1.7311x; 1.0269x over previous
#include <cuda_runtime.h>
#include <cstdint>

// Problem constants
#define BB     64
#define CC     20
#define NAA    5
#define HHH    19
#define WWW    19
#define HW     361      // 19*19
#define TT     50
#define NBB    1280     // B*C
#define A4     1805     // NA*H*W
#define CHN    30       // NA*(5+NCPA)
#define EPS12  1e-12f
#define RB     4                              // rows per band
#define BANDS  5
#define TILE   (NAA * RB * WWW)               // 380 cells per band-block
#define MAIN_BLOCKS (NBB * BANDS)             // 6400
#define CLS_N   (BB * A4)                     // 115520
#define CLS_BLOCKS ((CLS_N + 127) / 128)      // 903
#define TOTB    (MAIN_BLOCKS + CLS_BLOCKS)
#define BIGS    1e18f

// Static scratch (no allocations; self-cleaning or overwritten every run)
__device__ int    g_bm[NBB][BANDS];           // gts per (nb, band)
__device__ float4 g_bgt[NBB][BANDS][TT];      // gl, gr, gtop, gbot
__device__ float  g_bgc[NBB][BANDS][TT];      // -0.375*gt_area
__device__ int    g_bn[NBB][BANDS];           // assignments per (nb, band)
__device__ int    g_bcell[NBB][BANDS][TT];
__device__ float  g_bval[NBB][BANDS][TT][5];  // tx, ty, tw, th, tconf
__device__ int    g_cnt[CLS_N];               // winners per (b, a4) across C
__device__ float  g_tsum[CLS_N];
__device__ float  g_accf[3];                  // dense, cls nll, nsel (float)
__device__ unsigned int g_done;

__device__ __forceinline__ float fsigm(float v) {
    return __fdividef(1.0f, 1.0f + __expf(-v));
}

// ---------------------------------------------------------------------------
// One block (64 threads) per nb row. Computes gt boxes, winner assignments,
// and pre-compacts per-band gt lists + per-band assignment lists.
__global__ void k_assign(const float* __restrict__ out,
                         const float* __restrict__ target,
                         const float* __restrict__ anchors) {
    int nb = blockIdx.x;
    int t  = threadIdx.x;

    __shared__ float s_tg[TT * 5];
    __shared__ int   s_ng;
    __shared__ int   s_bm[BANDS], s_bn[BANDS];
    __shared__ int   s_cell[TT];

    if (t == 0) s_ng = TT;
    if (t < BANDS) { s_bm[t] = 0; s_bn[t] = 0; }
    const float* tg = target + (size_t)nb * TT * 5;
    for (int i = t; i < TT * 5; i += 64) s_tg[i] = tg[i];
    __syncthreads();

    if (t < TT && s_tg[t * 5 + 1] == 0.0f) atomicMin(&s_ng, t);
    __syncthreads();
    int ng = s_ng;

    float gx = 0.f, gy = 0.f, gw = 0.f, gh = 0.f, ct = 0.f;
    int gi = 0, gj = 0, bn = 0, cell = -1;
    float awb = 1.f, ahb = 1.f;

    if (t < ng) {
        ct = s_tg[t * 5 + 0];
        gx = s_tg[t * 5 + 1] * (float)WWW;
        gy = s_tg[t * 5 + 2] * (float)HHH;
        gw = s_tg[t * 5 + 3] * (float)WWW;
        gh = s_tg[t * 5 + 4] * (float)HHH;

        float best = -1.0f;
#pragma unroll
        for (int a = 0; a < NAA; a++) {
            float aw = __ldg(&anchors[2 * a]);
            float ah = __ldg(&anchors[2 * a + 1]);
            float inter = fminf(gw, aw) * fminf(gh, ah);
            float un = gw * gh + aw * ah - inter;
            float r = __fdividef(inter, fmaxf(un, EPS12));
            if (r > best) { best = r; bn = a; awb = aw; ahb = ah; }
        }
        gi = (int)gx;
        gj = (int)gy;
        cell = bn * HW + gj * WWW + gi;   // anchor-major cell id
        s_cell[t] = cell;

        // per-band gt list: gt matters only for rows hh in (gy-0.4gh-1, gy+0.4gh)
        float gl = gx - 0.5f * gw, gr = gx + 0.5f * gw;
        float gtop = gy - 0.5f * gh, gbot = gy + 0.5f * gh;
        float ylo = 0.9f * gtop + 0.1f * gbot;  // gy - 0.4*gh
        float yhi = 0.1f * gtop + 0.9f * gbot;  // gy + 0.4*gh
        float gcn = -0.375f * gw * gh;
#pragma unroll
        for (int bd = 0; bd < BANDS; bd++) {
            float h0 = (float)(bd * RB);
            if (h0 < yhi + 0.01f && h0 + (float)RB > ylo - 0.01f) {
                int pos = atomicAdd(&s_bm[bd], 1);
                g_bgt[nb][bd][pos] = make_float4(gl, gr, gtop, gbot);
                g_bgc[nb][bd][pos] = gcn;
            }
        }
    }
    __syncthreads();

    if (t < ng) {
        // last writer wins for this cell within this nb row
        bool win = true;
        for (int t2 = t + 1; t2 < ng; t2++)
            if (s_cell[t2] == cell) win = false;

        if (win) {
            int b = nb / CC;
            atomicAdd(&g_cnt[b * A4 + cell], 1);
            atomicAdd(&g_tsum[b * A4 + cell], ct);

            const float* ob = out + ((size_t)nb * CHN + bn * 6) * HW + gj * WWW + gi;
            float px = fsigm(ob[0])    + (float)gi;
            float py = fsigm(ob[HW])   + (float)gj;
            float pw = __expf(ob[2 * HW]) * awb;
            float ph = __expf(ob[3 * HW]) * ahb;

            float l  = fmaxf(gx - 0.5f * gw, px - 0.5f * pw);
            float r2 = fminf(gx + 0.5f * gw, px + 0.5f * pw);
            float tp = fmaxf(gy - 0.5f * gh, py - 0.5f * ph);
            float bt = fminf(gy + 0.5f * gh, py + 0.5f * ph);
            float inter = fmaxf(r2 - l, 0.0f) * fmaxf(bt - tp, 0.0f);
            float un = gw * gh + pw * ph - inter;
            float iou = __fdividef(inter, fmaxf(un, EPS12));

            int bd = gj / RB;
            int slot = atomicAdd(&s_bn[bd], 1);
            g_bcell[nb][bd][slot] = cell;
            g_bval[nb][bd][slot][0] = gx - (float)gi;
            g_bval[nb][bd][slot][1] = gy - (float)gj;
            g_bval[nb][bd][slot][2] = __logf(__fdividef(fmaxf(gw, EPS12), awb));
            g_bval[nb][bd][slot][3] = __logf(__fdividef(fmaxf(gh, EPS12), ahb));
            g_bval[nb][bd][slot][4] = iou;
        }
    }
    __syncthreads();
    if (t < BANDS) {
        g_bm[nb][t] = s_bm[t];
        g_bn[nb][t] = s_bn[t];
    }
}

// ---------------------------------------------------------------------------
// Fused dense losses (band-tiled, precompacted gts, 3 cells/thread) + class
// loss + final combine, ONE launch. All loop-independent loss terms are
// computed BEFORE the IoU loop so only 7 regs/cell stay live across it.
// Assigned cells encode cfm=1 as k1=+inf (loop can never set 'over').
__global__ void __launch_bounds__(128, 9)
k_fused(const float* __restrict__ out,
        const float* __restrict__ anchors,
        float* __restrict__ res) {
    int tid = threadIdx.x;

    if (blockIdx.x < MAIN_BLOCKS) {
        int nb   = blockIdx.x / BANDS;
        int band = blockIdx.x - nb * BANDS;
        int h0   = band * RB;

        // ---- shared tables (precompacted per band) ----
        __shared__ float4 s_g[TT];
        __shared__ float  s_gcn[TT];
        __shared__ int    s_cell[TT];
        __shared__ float  s_val[TT][5];
        __shared__ uint32_t s_bits[57];

        int m    = g_bm[nb][band];
        int nasg = g_bn[nb][band];
        int mp   = ((m + 4) / 5) * 5;

        if (tid < 57) s_bits[tid] = 0u;
        for (int i = tid; i < mp; i += 128) {
            if (i < m) {
                s_g[i]   = g_bgt[nb][band][i];
                s_gcn[i] = g_bgc[nb][band][i];
            } else {
                s_g[i]   = make_float4(0.f, 0.f, 0.f, 0.f);
                s_gcn[i] = -1e30f;
            }
        }
        for (int i = tid; i < nasg * 5; i += 128)
            (&s_val[0][0])[i] = (&g_bval[nb][band][0][0])[i];
        __syncthreads();
        for (int i = tid; i < nasg; i += 128) {
            int c = g_bcell[nb][band][i];
            s_cell[i] = c;
            atomicOr(&s_bits[c >> 5], 1u << (c & 31));
        }
        __syncthreads();

        // ---- per-cell: load, pre-compute ALL loop-independent loss ----
        float pl[3], pr[3], pt[3], pb[3], k1[3], mm[3], dcv[3];
        float contrib = 0.0f;
#pragma unroll
        for (int i = 0; i < 3; i++) {
            int c = tid + i * 128;
            int na = c / (RB * WWW);
            int rem = c - na * (RB * WWW);
            int r = rem / WWW;
            int ww = rem - r * WWW;
            int hh = h0 + r;
            bool live = (c < TILE) && (hh < HHH);
            mm[i] = -1e30f;
            if (live) {
                int hw = hh * WWW + ww;
                int idx = na * HW + hw;
                const float* ob = out + ((size_t)nb * CHN + na * 6) * HW + hw;
                float o0 = ob[0], o1 = ob[HW], o2 = ob[2 * HW],
                      o3 = ob[3 * HW], o4 = ob[4 * HW];

                float x = fsigm(o0), y = fsigm(o1), conf = fsigm(o4);
                float aw = __ldg(&anchors[2 * na]);
                float ah = __ldg(&anchors[2 * na + 1]);
                float px = x + (float)ww, py = y + (float)hh;
                float pw = __expf(o2) * aw, ph = __expf(o3) * ah;
                pl[i] = px - 0.5f * pw; pr[i] = px + 0.5f * pw;
                pt[i] = py - 0.5f * ph; pb[i] = py + 0.5f * ph;
                k1[i] = 0.375f * pw * ph;

                float tx = 0.5f, ty = 0.5f, tw = 0.0f, th = 0.0f, tconf = 0.0f;
                if (s_bits[idx >> 5] & (1u << (idx & 31))) {
                    for (int k = 0; k < nasg; k++) {
                        if (s_cell[k] == idx) {
                            tx = s_val[k][0]; ty = s_val[k][1];
                            tw = s_val[k][2]; th = s_val[k][3];
                            tconf = s_val[k][4];
                            k1[i] = 1e30f;   // assigned: conf term always on
                        }
                    }
                }
                // softplus(v) = -log(1 - sigmoid(v)); BCE = sp(v) - t*v
                float bxy = -__logf(1.0f - x) - tx * o0
                            - __logf(1.0f - y) - ty * o1;
                float dw = o2 - tw, dh = o3 - th;
                contrib += bxy + 0.5f * (dw * dw + dh * dh);
                dcv[i] = conf - tconf;
            } else {
                pl[i] = BIGS; pr[i] = -BIGS;
                pt[i] = BIGS; pb[i] = -BIGS;
                k1[i] = 1e30f;
                dcv[i] = 0.0f;
            }
        }

        // ---- filtered IoU>0.6 loop (9 ops/cell/iter, 3-way ILP) ----
#pragma unroll 5
        for (int t = 0; t < mp; t++) {
            float4 g = s_g[t];
            float gcn = s_gcn[t];
#pragma unroll
            for (int i = 0; i < 3; i++) {
                float iw = fminf(pr[i], g.y) - fmaxf(pl[i], g.x);
                float ih = fminf(pb[i], g.w) - fmaxf(pt[i], g.z);
                mm[i] = fmaxf(mm[i], fmaf(fmaxf(iw, 0.0f), ih, gcn));
            }
        }

        // ---- tiny epilogue: conf term only ----
#pragma unroll
        for (int i = 0; i < 3; i++) {
            float dc = (mm[i] > k1[i]) ? 0.0f : dcv[i];
            contrib += 0.5f * dc * dc;
        }

#pragma unroll
        for (int o = 16; o > 0; o >>= 1)
            contrib += __shfl_down_sync(0xffffffffu, contrib, o);
        __shared__ float s_red[4];
        if ((tid & 31) == 0) s_red[tid >> 5] = contrib;
        __syncthreads();
        if (tid == 0)
            atomicAdd(&g_accf[0], s_red[0] + s_red[1] + s_red[2] + s_red[3]);
    } else {
        // ---- class-loss blocks (self-cleaning: reset g_cnt/g_tsum) ----
        int idx = (blockIdx.x - MAIN_BLOCKS) * 128 + tid;
        float nll = 0.0f, ns = 0.0f;
        if (idx < CLS_N) {
            int cnt = g_cnt[idx];
            if (cnt != 0) {
                float tsum = g_tsum[idx];
                g_cnt[idx] = 0;
                g_tsum[idx] = 0.0f;
                if (cnt == 1) {
                    int b  = idx / A4;
                    int a4 = idx - b * A4;
                    int na = a4 / HW;
                    int hw = a4 - na * HW;
                    int label = (int)tsum;
                    size_t obase = ((size_t)b * CC * CHN + na * 6 + 5) * HW + hw;
                    float mv = -1e30f, s = 0.0f, llab = 0.0f;
#pragma unroll
                    for (int c = 0; c < CC; c++) {
                        float l = out[obase + (size_t)c * CHN * HW];
                        if (c == label) llab = l;
                        if (l > mv) { s = s * __expf(mv - l) + 1.0f; mv = l; }
                        else        { s += __expf(l - mv); }
                    }
                    float lse = mv + __logf(s);
                    nll = lse - llab;
                    ns  = 1.0f;
                }
            }
        }
#pragma unroll
        for (int o = 16; o > 0; o >>= 1) {
            nll += __shfl_down_sync(0xffffffffu, nll, o);
            ns  += __shfl_down_sync(0xffffffffu, ns,  o);
        }
        __shared__ float s_n[4], s_c[4];
        if ((tid & 31) == 0) { s_n[tid >> 5] = nll; s_c[tid >> 5] = ns; }
        __syncthreads();
        if (tid == 0) {
            float a = s_n[0] + s_n[1] + s_n[2] + s_n[3];
            float bsum = s_c[0] + s_c[1] + s_c[2] + s_c[3];
            if (a != 0.0f)    atomicAdd(&g_accf[1], a);
            if (bsum != 0.0f) atomicAdd(&g_accf[2], bsum);
        }
    }

    // ---- last-block final combine (also resets g_accf for next replay) ----
    if (tid == 0) {
        __threadfence();
        unsigned int old = atomicAdd(&g_done, 1u);
        if (old == TOTB - 1) {
            float a0 = atomicExch(&g_accf[0], 0.0f);
            float a1 = atomicExch(&g_accf[1], 0.0f);
            float a2 = atomicExch(&g_accf[2], 0.0f);
            double N = (double)NBB * (double)A4;
            res[0] = (float)((double)a0 / N +
                             (double)a1 / fmax((double)a2, 1.0));
            g_done = 0;
        }
    }
}

// ---------------------------------------------------------------------------
extern "C" void kernel_launch(void* const* d_in, const int* in_sizes, int n_in,
                              void* d_out, int out_size) {
    const float* out_t   = (const float*)d_in[0];
    const float* target  = (const float*)d_in[1];
    const float* anchors = (const float*)d_in[2];
    float* res = (float*)d_out;

    k_assign<<<NBB, 64>>>(out_t, target, anchors);
    k_fused<<<TOTB, 128>>>(out_t, anchors, res);
}